// round 8
// baseline (speedup 1.0000x reference)
#include <cuda_runtime.h>
#include <math.h>

// Collapsed classifier vectors: wv[c][d] = sum_j Wf[c,j] * W1[j,d],
// cc[c] = bf[c] + sum_j Wf[c,j] * b1[j]
__device__ float g_wv[2][128];
__device__ float g_cc[2];

// ---------------- packed f32x2 helpers ----------------
__device__ __forceinline__ void fma2(unsigned long long& d,
                                     unsigned long long a,
                                     unsigned long long b) {
    asm("fma.rn.f32x2 %0, %1, %2, %0;" : "+l"(d) : "l"(a), "l"(b));
}
__device__ __forceinline__ float2 unpack2(unsigned long long v) {
    float2 r;
    asm("mov.b64 {%0, %1}, %2;" : "=f"(r.x), "=f"(r.y) : "l"(v));
    return r;
}

// ---------------- prep: collapse W1/Wf/b1/bf ----------------
__global__ void prep_kernel(const float* __restrict__ W1,
                            const float* __restrict__ Wf,
                            const float* __restrict__ b1,
                            const float* __restrict__ bf) {
    int t = threadIdx.x;           // 256 threads: (c,d)
    int c = t >> 7;
    int d = t & 127;
    double s = 0.0;
    for (int j = 0; j < 128; j++)
        s += (double)Wf[c * 128 + j] * (double)W1[j * 128 + d];
    g_wv[c][d] = (float)s;
    if (t < 2) {
        double cs = 0.0;
        for (int j = 0; j < 128; j++)
            cs += (double)Wf[t * 128 + j] * (double)b1[j];
        g_cc[t] = (float)(cs + (double)bf[t]);
    }
}

// ---------------- main fused kernel ----------------
// Block: 128 edges x 128 hidden outputs, 256 threads = 16(tx) x 16(ty).
// Each thread: 8 edges (4 f32x2 pairs) x 8 dp accumulators.
// smem per 64-k chunk:
//   sp[64k][128e]            product tile (32 KB)
//   wbd[64k][8p][16tx][4]    W0 chunk PRE-DUPLICATED for f32x2 (64 KB):
//     wbd[k][p][tx][0..3] = { W0[tx*8+2p][kg], dup, W0[tx*8+2p+1][kg], dup }
//   -> GEMM inner loop: 2 A-LDS.128 + 4 B-LDS.128 (all conflict-free) + 32 FFMA2, ZERO movs.
// Sync cadence: 2 barriers per 64-k chunk, 8 chunks = 16 barriers total (same as R5 best).
__global__ void __launch_bounds__(256, 2)
advers_mask_edge_kernel(const float* __restrict__ h,
                        const float* __restrict__ W0,
                        const float* __restrict__ b0,
                        const float* __restrict__ u,
                        const int* __restrict__ src,
                        const int* __restrict__ dst,
                        float* __restrict__ out,
                        int E, int N) {
    extern __shared__ float smem_f[];
    float* sp  = smem_f;            // [64][128]  = 8192 floats
    float* wbd = smem_f + 8192;     // [64][8][16][4] = 16384 floats

    const int tid = threadIdx.x;
    const int tx  = tid & 15;      // dp group
    const int ty  = tid >> 4;      // edge group
    const int eb  = blockIdx.x * 128;

    const int el   = tid >> 1;     // 0..127: edge (sp build) / dp row (wbd build)
    const int half = tid & 1;

    // wbd store base for dp = el: p = (el&7)>>1, tx_el = el>>3, i = (el&1)*2
    const int wp   = (el & 7) >> 1;
    const int wtx  = el >> 3;
    const int wi   = (el & 1) * 2;
    float* wst = wbd + (wp * 16 + wtx) * 4 + wi;   // + k*256

    int eg = eb + el;
    int ec = (eg < E) ? eg : (E - 1);
    const int se = src[ec];
    const int de = dst[ec];

    unsigned long long acc[4][8];
#pragma unroll
    for (int i = 0; i < 4; i++)
#pragma unroll
        for (int j = 0; j < 8; j++) acc[i][j] = 0ull;

    const float* wk = wbd + tx * 4;
    const float* sprow = sp + ty * 8;

    for (int seg = 0; seg < 4; seg++) {
        const int l0 = seg >> 1;
        const int l1 = seg & 1;
        const float* hs = h + ((size_t)l0 * N + se) * 128;
        const float* hd = h + ((size_t)l1 * N + de) * 128;

        for (int ch = 0; ch < 2; ch++) {
            // (entry condition: previous chunk's GEMM finished -> trailing barrier below)

            // ---- build product tile sp[kh][e] = hs[kg]*hd[kg], kg = ch*64 + kh ----
            {
                const int dbase = ch * 64 + half * 32;
#pragma unroll
                for (int q = 0; q < 8; q++) {
                    int d = dbase + q * 4;
                    int kh = half * 32 + q * 4;
                    float4 va = *(const float4*)(hs + d);
                    float4 vb = *(const float4*)(hd + d);
                    sp[(kh + 0) * 128 + el] = va.x * vb.x;
                    sp[(kh + 1) * 128 + el] = va.y * vb.y;
                    sp[(kh + 2) * 128 + el] = va.z * vb.z;
                    sp[(kh + 3) * 128 + el] = va.w * vb.w;
                }
            }
            // ---- build duplicated W chunk: kg = seg*128 + ch*64 + kh ----
            {
                const float* ws = W0 + (size_t)el * 512 + seg * 128 + ch * 64 + half * 32;
#pragma unroll
                for (int q = 0; q < 8; q++) {
                    float4 w4 = *(const float4*)(ws + q * 4);
                    int kh = half * 32 + q * 4;
                    *(float2*)(wst + (kh + 0) * 256) = make_float2(w4.x, w4.x);
                    *(float2*)(wst + (kh + 1) * 256) = make_float2(w4.y, w4.y);
                    *(float2*)(wst + (kh + 2) * 256) = make_float2(w4.z, w4.z);
                    *(float2*)(wst + (kh + 3) * 256) = make_float2(w4.w, w4.w);
                }
            }
            __syncthreads();   // tiles visible to all

            // ---- 128e x 128dp x 64k f32x2 GEMM accumulate (no movs, no dups) ----
#pragma unroll 2
            for (int k = 0; k < 64; k++) {
                ulonglong2 a0 = *(const ulonglong2*)(sprow + k * 128);      // edges 0..3
                ulonglong2 a1 = *(const ulonglong2*)(sprow + k * 128 + 4);  // edges 4..7
                ulonglong2 b01 = *(const ulonglong2*)(wk + k * 256);        // dp 0,1 (dup)
                ulonglong2 b23 = *(const ulonglong2*)(wk + k * 256 + 64);   // dp 2,3
                ulonglong2 b45 = *(const ulonglong2*)(wk + k * 256 + 128);  // dp 4,5
                ulonglong2 b67 = *(const ulonglong2*)(wk + k * 256 + 192);  // dp 6,7
                fma2(acc[0][0], a0.x, b01.x); fma2(acc[0][1], a0.x, b01.y);
                fma2(acc[0][2], a0.x, b23.x); fma2(acc[0][3], a0.x, b23.y);
                fma2(acc[0][4], a0.x, b45.x); fma2(acc[0][5], a0.x, b45.y);
                fma2(acc[0][6], a0.x, b67.x); fma2(acc[0][7], a0.x, b67.y);
                fma2(acc[1][0], a0.y, b01.x); fma2(acc[1][1], a0.y, b01.y);
                fma2(acc[1][2], a0.y, b23.x); fma2(acc[1][3], a0.y, b23.y);
                fma2(acc[1][4], a0.y, b45.x); fma2(acc[1][5], a0.y, b45.y);
                fma2(acc[1][6], a0.y, b67.x); fma2(acc[1][7], a0.y, b67.y);
                fma2(acc[2][0], a1.x, b01.x); fma2(acc[2][1], a1.x, b01.y);
                fma2(acc[2][2], a1.x, b23.x); fma2(acc[2][3], a1.x, b23.y);
                fma2(acc[2][4], a1.x, b45.x); fma2(acc[2][5], a1.x, b45.y);
                fma2(acc[2][6], a1.x, b67.x); fma2(acc[2][7], a1.x, b67.y);
                fma2(acc[3][0], a1.y, b01.x); fma2(acc[3][1], a1.y, b01.y);
                fma2(acc[3][2], a1.y, b23.x); fma2(acc[3][3], a1.y, b23.y);
                fma2(acc[3][4], a1.y, b45.x); fma2(acc[3][5], a1.y, b45.y);
                fma2(acc[3][6], a1.y, b67.x); fma2(acc[3][7], a1.y, b67.y);
            }
            __syncthreads();   // all reads done before next chunk's builds
        }
    }

    // ---- epilogue: bias + relu + dual dot vs wv, reduce over tx, gumbel, argmax ----
    float wv0r[8], wv1r[8], bbr[8];
#pragma unroll
    for (int j = 0; j < 8; j++) {
        int dp = tx * 8 + j;
        wv0r[j] = g_wv[0][dp];
        wv1r[j] = g_wv[1][dp];
        bbr[j]  = b0[dp];
    }
    const float cc0 = g_cc[0];
    const float cc1 = g_cc[1];

#pragma unroll
    for (int i = 0; i < 4; i++) {
        float s0a = 0.f, s1a = 0.f, s0b = 0.f, s1b = 0.f;
#pragma unroll
        for (int j = 0; j < 8; j++) {
            float2 xv = unpack2(acc[i][j]);
            float xa = fmaxf(xv.x + bbr[j], 0.f);
            float xb = fmaxf(xv.y + bbr[j], 0.f);
            s0a = fmaf(xa, wv0r[j], s0a);
            s1a = fmaf(xa, wv1r[j], s1a);
            s0b = fmaf(xb, wv0r[j], s0b);
            s1b = fmaf(xb, wv1r[j], s1b);
        }
        // reduce over the 16 tx lanes (xor stays inside each 16-lane half-warp)
#pragma unroll
        for (int off = 8; off; off >>= 1) {
            s0a += __shfl_xor_sync(0xffffffffu, s0a, off);
            s1a += __shfl_xor_sync(0xffffffffu, s1a, off);
            s0b += __shfl_xor_sync(0xffffffffu, s0b, off);
            s1b += __shfl_xor_sync(0xffffffffu, s1b, off);
        }
        if (tx == 0) {
            int e0 = eb + ty * 8 + i * 2;
#pragma unroll
            for (int lane = 0; lane < 2; lane++) {
                int e = e0 + lane;
                if (e < E) {
                    float s0 = lane ? s0b : s0a;
                    float s1 = lane ? s1b : s1a;
                    float u0 = u[2 * e];
                    float u1 = u[2 * e + 1];
                    float gg0 = -logf(-logf(u0 + 1e-10f) + 1e-10f);
                    float gg1 = -logf(-logf(u1 + 1e-10f) + 1e-10f);
                    float v0 = s0 + cc0 + gg0;
                    float v1 = s1 + cc1 + gg1;
                    // jnp.argmax ties -> index 0; class 1 only if strictly greater
                    bool one = (v1 > v0);
                    out[2 * e]     = one ? 0.f : 1.f;
                    out[2 * e + 1] = one ? 1.f : 0.f;
                }
            }
        }
    }
}

extern "C" void kernel_launch(void* const* d_in, const int* in_sizes, int n_in,
                              void* d_out, int out_size) {
    const float* h  = (const float*)d_in[0];
    const float* W0 = (const float*)d_in[1];
    const float* b0 = (const float*)d_in[2];
    const float* W1 = (const float*)d_in[3];
    const float* b1 = (const float*)d_in[4];
    const float* Wf = (const float*)d_in[5];
    const float* bf = (const float*)d_in[6];
    const float* u  = (const float*)d_in[7];
    const int*   src = (const int*)d_in[8];
    const int*   dst = (const int*)d_in[9];
    float* out = (float*)d_out;

    const int E = in_sizes[8];
    const int N = in_sizes[0] / 256;   // h is (L=2, N, D=128)

    prep_kernel<<<1, 256>>>(W1, Wf, b1, bf);

    const size_t smem = (size_t)(8192 + 16384) * sizeof(float);  // 96 KB
    cudaFuncSetAttribute(advers_mask_edge_kernel,
                         cudaFuncAttributeMaxDynamicSharedMemorySize, (int)smem);

    int blocks = (E + 127) / 128;
    advers_mask_edge_kernel<<<blocks, 256, smem>>>(h, W0, b0, u, src, dst, out, E, N);
}

// round 10
// speedup vs baseline: 1.4321x; 1.4321x over previous
#include <cuda_runtime.h>
#include <cuda_bf16.h>
#include <math.h>
#include <stdint.h>

// ---------------- device globals (allowed scratch) ----------------
__device__ float g_wv[2][128];   // wv[c] = Wf[c] @ W1
__device__ float g_cc[2];        // cc[c] = bf[c] + Wf[c] @ b1
// Pre-swizzled images of W0 bf16 splits: [seg][split] = 128dp x 128k tile (32KB each)
__device__ __nv_bfloat16 g_w0img[4][3][16384];

// Row-major [128][128] bf16 tile with XOR swizzle for conflict-free ldmatrix.
// row stride 256B; 16B granule swizzle: off = row*256 + (kByte ^ ((row&7)<<4))
__host__ __device__ __forceinline__ uint32_t swz(int row, int kByte) {
    return (uint32_t)row * 256u + (uint32_t)(kByte ^ ((row & 7) << 4));
}

// ---------------- PTX helpers (all sm_80+, legal on plain sm_100) ----------------
__device__ __forceinline__ uint32_t smem_u32(const void* p) {
    uint32_t a;
    asm("{ .reg .u64 t; cvta.to.shared.u64 t, %1; cvt.u32.u64 %0, t; }" : "=r"(a) : "l"(p));
    return a;
}
__device__ __forceinline__ void ldsm_x4(uint32_t* d, uint32_t addr) {
    asm volatile("ldmatrix.sync.aligned.m8n8.x4.shared.b16 {%0,%1,%2,%3}, [%4];"
                 : "=r"(d[0]), "=r"(d[1]), "=r"(d[2]), "=r"(d[3]) : "r"(addr));
}
__device__ __forceinline__ void mma_bf16(float* c, const uint32_t* a, uint32_t b0, uint32_t b1) {
    asm volatile(
        "mma.sync.aligned.m16n8k16.row.col.f32.bf16.bf16.f32 "
        "{%0,%1,%2,%3}, {%4,%5,%6,%7}, {%8,%9}, {%0,%1,%2,%3};"
        : "+f"(c[0]), "+f"(c[1]), "+f"(c[2]), "+f"(c[3])
        : "r"(a[0]), "r"(a[1]), "r"(a[2]), "r"(a[3]), "r"(b0), "r"(b1));
}
// pack two f32 into bf16x2 (lo = p0, hi = p1), round-to-nearest
__device__ __forceinline__ uint32_t pack_bf16x2(float p0, float p1) {
    uint32_t c;
    asm("cvt.rn.bf16x2.f32 %0, %1, %2;" : "=r"(c) : "f"(p1), "f"(p0));
    return c;
}

// ---------------- prep 1: collapse W1/Wf/b1/bf ----------------
__global__ void prep_kernel(const float* __restrict__ W1, const float* __restrict__ Wf,
                            const float* __restrict__ b1, const float* __restrict__ bf) {
    int t = threadIdx.x;    // 256 = (c, d)
    int c = t >> 7, d = t & 127;
    double s = 0.0;
    for (int j = 0; j < 128; j++)
        s += (double)Wf[c * 128 + j] * (double)W1[j * 128 + d];
    g_wv[c][d] = (float)s;
    if (t < 2) {
        double cs = 0.0;
        for (int j = 0; j < 128; j++)
            cs += (double)Wf[t * 128 + j] * (double)b1[j];
        g_cc[t] = (float)(cs + (double)bf[t]);
    }
}

// ---------------- prep 2: split W0 into 3 bf16 images, pre-swizzled ----------------
__global__ void prep_w0_kernel(const float* __restrict__ W0) {
    int idx = blockIdx.x * blockDim.x + threadIdx.x;   // 65536 = 4seg*128dp*128k
    int seg = idx >> 14;
    int dp  = (idx >> 7) & 127;
    int k   = idx & 127;
    float w = W0[dp * 512 + seg * 128 + k];
    __nv_bfloat16 v0 = __float2bfloat16(w);
    float r1 = w - __bfloat162float(v0);
    __nv_bfloat16 v1 = __float2bfloat16(r1);
    float r2 = r1 - __bfloat162float(v1);
    __nv_bfloat16 v2 = __float2bfloat16(r2);
    uint32_t o = swz(dp, k * 2) >> 1;
    g_w0img[seg][0][o] = v0;
    g_w0img[seg][1][o] = v1;
    g_w0img[seg][2][o] = v2;
}

// ---------------- main kernel ----------------
// Block: 128 edges x 128 dp, 256 threads = 8 warps. Warp tile: 32e x 64dp.
// Warp grid: we = wid>>1 (edge group), wd = wid&1 (dp half).
// smem:
//   [0, 98304)       A split tiles: 3 x (128e x 128k bf16, swizzled row-major)
//   [98304, 196608)  B split tiles: 3 x 32KB (linear copy of g_w0img[seg])
//   [196608, 198144) consts: b0[128], wv0[128], wv1[128]
//   [198144, 200192) s_red[2][128][2]
#define SM_A     0
#define SM_B     98304
#define SM_CONST 196608
#define SM_RED   198144
#define SM_TOTAL 200192

__global__ void __launch_bounds__(256, 1)
advers_mask_edge_mma(const float* __restrict__ h,
                     const float* __restrict__ b0,
                     const float* __restrict__ u,
                     const int* __restrict__ src,
                     const int* __restrict__ dst,
                     float* __restrict__ out,
                     int E, int N) {
    extern __shared__ char smem[];
    const uint32_t sbase = smem_u32(smem);
    float* sc   = (float*)(smem + SM_CONST);
    float* sred = (float*)(smem + SM_RED);

    const int tid = threadIdx.x;
    const int wid = tid >> 5;
    const int lid = tid & 31;
    const int we  = wid >> 1;     // 0..3
    const int wd  = wid & 1;      // 0..1
    const int eb  = blockIdx.x * 128;

    // epilogue constants -> smem
    if (tid < 128) {
        sc[tid]       = b0[tid];
        sc[128 + tid] = g_wv[0][tid];
        sc[256 + tid] = g_wv[1][tid];
    }

    // A-build assignment: 2 threads per edge (k halves of 64)
    const int e_local = tid >> 1;
    const int khalf   = (tid & 1) * 64;
    int eg = eb + e_local;
    int ec = (eg < E) ? eg : (E - 1);
    const int se = src[ec];
    const int de = dst[ec];

    // ldmatrix per-lane addressing
    const int g = lid >> 3, r = lid & 7;
    // A x4: rowoff=(g&1)*8, koff=(g>>1)*8  -> regs {a0,a1,a2,a3}
    uint32_t aRowTerm[2];
#pragma unroll
    for (int mt = 0; mt < 2; mt++)
        aRowTerm[mt] = (uint32_t)(we * 32 + mt * 16 + (g & 1) * 8 + r) * 256u;
    // B x4: rowoff=(g>>1)*8, koff=(g&1)*8 -> regs {b0(n),b1(n),b0(n+8),b1(n+8)}
    uint32_t bRowTerm[4];
#pragma unroll
    for (int nt2 = 0; nt2 < 4; nt2++)
        bRowTerm[nt2] = (uint32_t)(wd * 64 + nt2 * 16 + (g >> 1) * 8 + r) * 256u;
    const uint32_t aKsel = (uint32_t)((g >> 1) * 16);
    const uint32_t bKsel = (uint32_t)((g & 1) * 16);
    const uint32_t rx    = (uint32_t)(r << 4);

    float acc[2][8][4];
#pragma unroll
    for (int mt = 0; mt < 2; mt++)
#pragma unroll
        for (int nt = 0; nt < 8; nt++)
#pragma unroll
            for (int i = 0; i < 4; i++) acc[mt][nt][i] = 0.f;

    const int comboA[6] = {0, 0, 1, 1, 0, 2};
    const int comboB[6] = {0, 1, 0, 1, 2, 0};

    for (int seg = 0; seg < 4; seg++) {
        const int l0 = seg >> 1, l1 = seg & 1;
        const float* hs = h + ((size_t)l0 * N + se) * 128 + seg * 0;  // full row; seg selects k below
        const float* hd = h + ((size_t)l1 * N + de) * 128;

        // ---- build A: product + 3-way exact bf16 split, swizzled row-major ----
#pragma unroll
        for (int q = 0; q < 8; q++) {
            const int col = khalf + q * 8;           // k within seg (h row uses same 128 dims)
            float4 a1 = *(const float4*)(hs + col);
            float4 a2 = *(const float4*)(hs + col + 4);
            float4 d1 = *(const float4*)(hd + col);
            float4 d2 = *(const float4*)(hd + col + 4);
            float p[8] = {a1.x * d1.x, a1.y * d1.y, a1.z * d1.z, a1.w * d1.w,
                          a2.x * d2.x, a2.y * d2.y, a2.z * d2.z, a2.w * d2.w};
            uint32_t u0[4], u1[4], u2[4];
#pragma unroll
            for (int pi = 0; pi < 4; pi++) {
                float p0 = p[2 * pi], p1 = p[2 * pi + 1];
                uint32_t c0 = pack_bf16x2(p0, p1);
                float r0 = p0 - __int_as_float(c0 << 16);
                float r1f = p1 - __int_as_float(c0 & 0xffff0000u);
                uint32_t c1 = pack_bf16x2(r0, r1f);
                float t0 = r0 - __int_as_float(c1 << 16);
                float t1 = r1f - __int_as_float(c1 & 0xffff0000u);
                uint32_t c2 = pack_bf16x2(t0, t1);
                u0[pi] = c0; u1[pi] = c1; u2[pi] = c2;
            }
            uint32_t soff = swz(e_local, col * 2);
            *(uint4*)(smem + SM_A + soff)         = make_uint4(u0[0], u0[1], u0[2], u0[3]);
            *(uint4*)(smem + SM_A + 32768 + soff) = make_uint4(u1[0], u1[1], u1[2], u1[3]);
            *(uint4*)(smem + SM_A + 65536 + soff) = make_uint4(u2[0], u2[1], u2[2], u2[3]);
        }

        // ---- copy B split images (pre-swizzled, linear 96KB) ----
        {
            const uint4* bsrc = (const uint4*)&g_w0img[seg][0][0];
            uint4* bdst = (uint4*)(smem + SM_B);
            for (int i = tid; i < 6144; i += 256) bdst[i] = bsrc[i];
        }
        __syncthreads();

        // ---- 8 K-steps of 16; 6 split-combos x 16 HMMA each ----
        for (int kst = 0; kst < 8; kst++) {
            const uint32_t kb = (uint32_t)(kst * 32);
            const uint32_t akb = (kb + aKsel) ^ rx;
            const uint32_t bkb = (kb + bKsel) ^ rx;

            uint32_t afr[3][2][4];
#pragma unroll
            for (int s = 0; s < 3; s++)
#pragma unroll
                for (int mt = 0; mt < 2; mt++)
                    ldsm_x4(afr[s][mt], sbase + SM_A + s * 32768 + aRowTerm[mt] + akb);

            uint32_t bfr[3][4][4];
#pragma unroll
            for (int s = 0; s < 3; s++)
#pragma unroll
                for (int nt2 = 0; nt2 < 4; nt2++)
                    ldsm_x4(bfr[s][nt2], sbase + SM_B + s * 32768 + bRowTerm[nt2] + bkb);

#pragma unroll
            for (int c = 0; c < 6; c++) {
                const int cA = comboA[c], cB = comboB[c];
#pragma unroll
                for (int mt = 0; mt < 2; mt++)
#pragma unroll
                    for (int nt2 = 0; nt2 < 4; nt2++) {
                        mma_bf16(acc[mt][nt2 * 2 + 0], afr[cA][mt],
                                 bfr[cB][nt2][0], bfr[cB][nt2][1]);
                        mma_bf16(acc[mt][nt2 * 2 + 1], afr[cA][mt],
                                 bfr[cB][nt2][2], bfr[cB][nt2][3]);
                    }
            }
        }
        __syncthreads();   // all reads done before next seg's builds
    }

    // ---- epilogue: relu + dual dot from C fragments ----
    // C frag: c0,c1 = row (lid>>2), cols tig*2,+1 ; c2,c3 = row+8
    const int tig = lid & 3;
#pragma unroll
    for (int mt = 0; mt < 2; mt++) {
#pragma unroll
        for (int hr = 0; hr < 2; hr++) {
            float s0 = 0.f, s1 = 0.f;
#pragma unroll
            for (int nt = 0; nt < 8; nt++) {
                int dp0 = wd * 64 + (nt >> 1) * 16 + (nt & 1) * 8 + tig * 2;
                float x0 = fmaxf(acc[mt][nt][hr * 2 + 0] + sc[dp0], 0.f);
                float x1 = fmaxf(acc[mt][nt][hr * 2 + 1] + sc[dp0 + 1], 0.f);
                s0 = fmaf(x0, sc[128 + dp0], fmaf(x1, sc[128 + dp0 + 1], s0));
                s1 = fmaf(x0, sc[256 + dp0], fmaf(x1, sc[256 + dp0 + 1], s1));
            }
            s0 += __shfl_xor_sync(0xffffffffu, s0, 1);
            s0 += __shfl_xor_sync(0xffffffffu, s0, 2);
            s1 += __shfl_xor_sync(0xffffffffu, s1, 1);
            s1 += __shfl_xor_sync(0xffffffffu, s1, 2);
            if (tig == 0) {
                int e_row = we * 32 + mt * 16 + hr * 8 + (lid >> 2);
                sred[(wd * 128 + e_row) * 2 + 0] = s0;
                sred[(wd * 128 + e_row) * 2 + 1] = s1;
            }
        }
    }
    __syncthreads();

    if (tid < 128) {
        int e = eb + tid;
        if (e < E) {
            float s0 = sred[tid * 2 + 0] + sred[(128 + tid) * 2 + 0];
            float s1 = sred[tid * 2 + 1] + sred[(128 + tid) * 2 + 1];
            float u0 = u[2 * e], u1 = u[2 * e + 1];
            float gg0 = -logf(-logf(u0 + 1e-10f) + 1e-10f);
            float gg1 = -logf(-logf(u1 + 1e-10f) + 1e-10f);
            float v0 = s0 + g_cc[0] + gg0;
            float v1 = s1 + g_cc[1] + gg1;
            bool one = (v1 > v0);   // argmax ties -> class 0
            out[2 * e]     = one ? 0.f : 1.f;
            out[2 * e + 1] = one ? 1.f : 0.f;
        }
    }
}

extern "C" void kernel_launch(void* const* d_in, const int* in_sizes, int n_in,
                              void* d_out, int out_size) {
    const float* h  = (const float*)d_in[0];
    const float* W0 = (const float*)d_in[1];
    const float* b0 = (const float*)d_in[2];
    const float* W1 = (const float*)d_in[3];
    const float* b1 = (const float*)d_in[4];
    const float* Wf = (const float*)d_in[5];
    const float* bf = (const float*)d_in[6];
    const float* u  = (const float*)d_in[7];
    const int*   src = (const int*)d_in[8];
    const int*   dst = (const int*)d_in[9];
    float* out = (float*)d_out;

    const int E = in_sizes[8];
    const int N = in_sizes[0] / 256;   // h is (L=2, N, D=128)

    prep_kernel<<<1, 256>>>(W1, Wf, b1, bf);
    prep_w0_kernel<<<256, 256>>>(W0);

    cudaFuncSetAttribute(advers_mask_edge_mma,
                         cudaFuncAttributeMaxDynamicSharedMemorySize, SM_TOTAL);
    int blocks = (E + 127) / 128;
    advers_mask_edge_mma<<<blocks, 256, SM_TOTAL>>>(h, b0, u, src, dst, out, E, N);
}

// round 12
// speedup vs baseline: 2.2032x; 1.5385x over previous
#include <cuda_runtime.h>
#include <cuda_fp16.h>
#include <math.h>
#include <stdint.h>

// ---------------- device globals (allowed scratch) ----------------
__device__ float g_wv[2][128];   // wv[c] = Wf[c] @ W1
__device__ float g_cc[2];        // cc[c] = bf[c] + Wf[c] @ b1
// Pre-swizzled images of W0 fp16 splits: [seg][split] = 128dp x 128k tile (32KB each)
__device__ __half g_w0img[4][2][16384];

// Row-major [128][128] fp16 tile with XOR swizzle for conflict-free ldmatrix.
// row stride 256B; 16B granule swizzle: off = row*256 + (kByte ^ ((row&7)<<4))
__host__ __device__ __forceinline__ uint32_t swz(int row, int kByte) {
    return (uint32_t)row * 256u + (uint32_t)(kByte ^ ((row & 7) << 4));
}

// ---------------- PTX helpers (sm_80+, legal on plain sm_100) ----------------
__device__ __forceinline__ uint32_t smem_u32(const void* p) {
    uint32_t a;
    asm("{ .reg .u64 t; cvta.to.shared.u64 t, %1; cvt.u32.u64 %0, t; }" : "=r"(a) : "l"(p));
    return a;
}
__device__ __forceinline__ void ldsm_x4(uint32_t* d, uint32_t addr) {
    asm volatile("ldmatrix.sync.aligned.m8n8.x4.shared.b16 {%0,%1,%2,%3}, [%4];"
                 : "=r"(d[0]), "=r"(d[1]), "=r"(d[2]), "=r"(d[3]) : "r"(addr));
}
__device__ __forceinline__ void mma_fp16(float* c, const uint32_t* a, uint32_t b0, uint32_t b1) {
    asm volatile(
        "mma.sync.aligned.m16n8k16.row.col.f32.f16.f16.f32 "
        "{%0,%1,%2,%3}, {%4,%5,%6,%7}, {%8,%9}, {%0,%1,%2,%3};"
        : "+f"(c[0]), "+f"(c[1]), "+f"(c[2]), "+f"(c[3])
        : "r"(a[0]), "r"(a[1]), "r"(a[2]), "r"(a[3]), "r"(b0), "r"(b1));
}

// ---------------- fused prep: W1/Wf collapse + W0 fp16 split images ----------------
// grid = 257 blocks x 256 thr. Blocks 0..255: W0 split/swizzle. Block 256: wv collapse.
__global__ void prep_all_kernel(const float* __restrict__ W0,
                                const float* __restrict__ W1,
                                const float* __restrict__ Wf,
                                const float* __restrict__ b1,
                                const float* __restrict__ bf) {
    if (blockIdx.x < 256) {
        int idx = blockIdx.x * 256 + threadIdx.x;   // 65536 = 4seg*128dp*128k
        int seg = idx >> 14;
        int dp  = (idx >> 7) & 127;
        int k   = idx & 127;
        float w = W0[dp * 512 + seg * 128 + k];
        __half v0 = __float2half_rn(w);
        float r1 = w - __half2float(v0);
        __half v1 = __float2half_rn(r1);
        uint32_t o = swz(dp, k * 2) >> 1;
        g_w0img[seg][0][o] = v0;
        g_w0img[seg][1][o] = v1;
    } else {
        int t = threadIdx.x;    // 256 = (c, d)
        int c = t >> 7, d = t & 127;
        double s = 0.0;
        for (int j = 0; j < 128; j++)
            s += (double)Wf[c * 128 + j] * (double)W1[j * 128 + d];
        g_wv[c][d] = (float)s;
        if (t < 2) {
            double cs = 0.0;
            for (int j = 0; j < 128; j++)
                cs += (double)Wf[t * 128 + j] * (double)b1[j];
            g_cc[t] = (float)(cs + (double)bf[t]);
        }
    }
}

// ---------------- main kernel ----------------
// Block: 128 edges x 128 dp, 256 threads = 8 warps. Warp tile: 32e x 64dp.
// Warp grid: we = wid>>1 (edge group), wd = wid&1 (dp half).
// K loop: 4 segs x 128k; per seg A (2 fp16 splits, full 128k) built once,
//         B staged per 64-k half-chunk (2 splits x 16KB, row stride 128B).
// smem:
//   [0,      65536)   A split tiles: 2 x (128e x 128k fp16, swizzled, stride 256B)
//   [65536,  98304)   B half-chunk: 2 x (128dp x 64k fp16, swizzled, stride 128B)
//   [98304,  99840)   consts: b0[128], wv0[128], wv1[128]
//   [99840, 101888)   s_red[2][128][2]
#define SM_A     0
#define SM_B     65536
#define SM_CONST 98304
#define SM_RED   99840
#define SM_TOTAL 101888

__global__ void __launch_bounds__(256, 2)
advers_mask_edge_mma(const float* __restrict__ h,
                     const float* __restrict__ b0,
                     const float* __restrict__ u,
                     const int* __restrict__ src,
                     const int* __restrict__ dst,
                     float* __restrict__ out,
                     int E, int N) {
    extern __shared__ char smem[];
    const uint32_t sbase = smem_u32(smem);
    float* sc   = (float*)(smem + SM_CONST);
    float* sred = (float*)(smem + SM_RED);

    const int tid = threadIdx.x;
    const int wid = tid >> 5;
    const int lid = tid & 31;
    const int we  = wid >> 1;     // 0..3
    const int wd  = wid & 1;      // 0..1
    const int eb  = blockIdx.x * 128;

    // epilogue constants -> smem
    if (tid < 128) {
        sc[tid]       = b0[tid];
        sc[128 + tid] = g_wv[0][tid];
        sc[256 + tid] = g_wv[1][tid];
    }

    // A-build assignment: 2 threads per edge (k halves of 64)
    const int e_local = tid >> 1;
    const int khalf   = (tid & 1) * 64;
    int eg = eb + e_local;
    int ec = (eg < E) ? eg : (E - 1);
    const int se = src[ec];
    const int de = dst[ec];

    // ldmatrix per-lane addressing (identical fragment mapping to R9, which passed)
    const int g = lid >> 3, r = lid & 7;
    uint32_t aRowTerm[2];
#pragma unroll
    for (int mt = 0; mt < 2; mt++)
        aRowTerm[mt] = (uint32_t)(we * 32 + mt * 16 + (g & 1) * 8 + r) * 256u;
    uint32_t bRowTerm[4];
#pragma unroll
    for (int nt2 = 0; nt2 < 4; nt2++)
        bRowTerm[nt2] = (uint32_t)(wd * 64 + nt2 * 16 + (g >> 1) * 8 + r) * 128u;  // stride 128B
    const uint32_t aKsel = (uint32_t)((g >> 1) * 16);
    const uint32_t bKsel = (uint32_t)((g & 1) * 16);
    const uint32_t rx    = (uint32_t)(r << 4);

    float acc[2][8][4];
#pragma unroll
    for (int mt = 0; mt < 2; mt++)
#pragma unroll
        for (int nt = 0; nt < 8; nt++)
#pragma unroll
            for (int i = 0; i < 4; i++) acc[mt][nt][i] = 0.f;

    for (int seg = 0; seg < 4; seg++) {
        const int l0 = seg >> 1, l1 = seg & 1;
        const float* hs = h + ((size_t)l0 * N + se) * 128;
        const float* hd = h + ((size_t)l1 * N + de) * 128;

        // ---- build A: product + 2-level exact fp16 split, swizzled row-major ----
#pragma unroll
        for (int q = 0; q < 8; q++) {
            const int col = khalf + q * 8;
            float4 a1 = *(const float4*)(hs + col);
            float4 a2 = *(const float4*)(hs + col + 4);
            float4 d1 = *(const float4*)(hd + col);
            float4 d2 = *(const float4*)(hd + col + 4);
            float p[8] = {a1.x * d1.x, a1.y * d1.y, a1.z * d1.z, a1.w * d1.w,
                          a2.x * d2.x, a2.y * d2.y, a2.z * d2.z, a2.w * d2.w};
            uint32_t u0[4], u1[4];
#pragma unroll
            for (int pi = 0; pi < 4; pi++) {
                float p0 = p[2 * pi], p1 = p[2 * pi + 1];
                __half h0a = __float2half_rn(p0);
                __half h0b = __float2half_rn(p1);
                float r0 = p0 - __half2float(h0a);
                float r1f = p1 - __half2float(h0b);
                __half h1a = __float2half_rn(r0);
                __half h1b = __float2half_rn(r1f);
                u0[pi] = (uint32_t)__half_as_ushort(h0a) | ((uint32_t)__half_as_ushort(h0b) << 16);
                u1[pi] = (uint32_t)__half_as_ushort(h1a) | ((uint32_t)__half_as_ushort(h1b) << 16);
            }
            uint32_t soff = swz(e_local, col * 2);
            *(uint4*)(smem + SM_A + soff)         = make_uint4(u0[0], u0[1], u0[2], u0[3]);
            *(uint4*)(smem + SM_A + 32768 + soff) = make_uint4(u1[0], u1[1], u1[2], u1[3]);
        }

        for (int chk = 0; chk < 2; chk++) {
            // ---- copy B half-chunk: 2 splits x 128 rows x 8 granules = 2048 x 16B ----
            // (swizzle XOR only touches bits [4:6], so each 128B half keeps its
            //  swizzle pattern; consumer reads with stride-128B rows + ^rx)
            {
                const char* bsrc = (const char*)&g_w0img[seg][0][0];
                for (int i = tid; i < 2048; i += 256) {
                    int s   = i >> 10;                        // split
                    int j   = i & 1023;
                    int row = j >> 3;                         // 0..127
                    int gg  = j & 7;                          // 16B granule in 128B half
                    *(uint4*)(smem + SM_B + s * 16384 + row * 128 + gg * 16) =
                        *(const uint4*)(bsrc + s * 32768 + row * 256 + chk * 128 + gg * 16);
                }
            }
            __syncthreads();

            // ---- 4 K-steps of 16; 3 split-combos (a0b0, a0b1, a1b0) ----
            for (int kst = 0; kst < 4; kst++) {
                const uint32_t akb = (uint32_t)((chk * 4 + kst) * 32 + aKsel) ^ rx;
                const uint32_t bkb = (uint32_t)(kst * 32 + bKsel) ^ rx;

                uint32_t afr[2][2][4];
#pragma unroll
                for (int s = 0; s < 2; s++)
#pragma unroll
                    for (int mt = 0; mt < 2; mt++)
                        ldsm_x4(afr[s][mt], sbase + SM_A + s * 32768 + aRowTerm[mt] + akb);

#pragma unroll
                for (int nt2 = 0; nt2 < 4; nt2++) {
                    uint32_t bf0[4], bf1[4];
                    ldsm_x4(bf0, sbase + SM_B + bRowTerm[nt2] + bkb);            // split 0
                    ldsm_x4(bf1, sbase + SM_B + 16384 + bRowTerm[nt2] + bkb);    // split 1
#pragma unroll
                    for (int mt = 0; mt < 2; mt++) {
                        float* c0 = acc[mt][nt2 * 2 + 0];
                        float* c1 = acc[mt][nt2 * 2 + 1];
                        mma_fp16(c0, afr[0][mt], bf0[0], bf0[1]);   // a0*b0
                        mma_fp16(c1, afr[0][mt], bf0[2], bf0[3]);
                        mma_fp16(c0, afr[0][mt], bf1[0], bf1[1]);   // a0*b1
                        mma_fp16(c1, afr[0][mt], bf1[2], bf1[3]);
                        mma_fp16(c0, afr[1][mt], bf0[0], bf0[1]);   // a1*b0
                        mma_fp16(c1, afr[1][mt], bf0[2], bf0[3]);
                    }
                }
            }
            __syncthreads();   // B chunk reads done before overwrite (and A before next seg build)
        }
    }

    // ---- epilogue: relu + dual dot from C fragments (mapping verified in R9) ----
    const int tig = lid & 3;
#pragma unroll
    for (int mt = 0; mt < 2; mt++) {
#pragma unroll
        for (int hr = 0; hr < 2; hr++) {
            float s0 = 0.f, s1 = 0.f;
#pragma unroll
            for (int nt = 0; nt < 8; nt++) {
                int dp0 = wd * 64 + (nt >> 1) * 16 + (nt & 1) * 8 + tig * 2;
                float x0 = fmaxf(acc[mt][nt][hr * 2 + 0] + sc[dp0], 0.f);
                float x1 = fmaxf(acc[mt][nt][hr * 2 + 1] + sc[dp0 + 1], 0.f);
                s0 = fmaf(x0, sc[128 + dp0], fmaf(x1, sc[128 + dp0 + 1], s0));
                s1 = fmaf(x0, sc[256 + dp0], fmaf(x1, sc[256 + dp0 + 1], s1));
            }
            s0 += __shfl_xor_sync(0xffffffffu, s0, 1);
            s0 += __shfl_xor_sync(0xffffffffu, s0, 2);
            s1 += __shfl_xor_sync(0xffffffffu, s1, 1);
            s1 += __shfl_xor_sync(0xffffffffu, s1, 2);
            if (tig == 0) {
                int e_row = we * 32 + mt * 16 + hr * 8 + (lid >> 2);
                sred[(wd * 128 + e_row) * 2 + 0] = s0;
                sred[(wd * 128 + e_row) * 2 + 1] = s1;
            }
        }
    }
    __syncthreads();

    if (tid < 128) {
        int e = eb + tid;
        if (e < E) {
            float s0 = sred[tid * 2 + 0] + sred[(128 + tid) * 2 + 0];
            float s1 = sred[tid * 2 + 1] + sred[(128 + tid) * 2 + 1];
            float u0 = u[2 * e], u1 = u[2 * e + 1];
            float gg0 = -logf(-logf(u0 + 1e-10f) + 1e-10f);
            float gg1 = -logf(-logf(u1 + 1e-10f) + 1e-10f);
            float v0 = s0 + g_cc[0] + gg0;
            float v1 = s1 + g_cc[1] + gg1;
            bool one = (v1 > v0);   // argmax ties -> class 0
            out[2 * e]     = one ? 0.f : 1.f;
            out[2 * e + 1] = one ? 1.f : 0.f;
        }
    }
}

extern "C" void kernel_launch(void* const* d_in, const int* in_sizes, int n_in,
                              void* d_out, int out_size) {
    const float* h  = (const float*)d_in[0];
    const float* W0 = (const float*)d_in[1];
    const float* b0 = (const float*)d_in[2];
    const float* W1 = (const float*)d_in[3];
    const float* b1 = (const float*)d_in[4];
    const float* Wf = (const float*)d_in[5];
    const float* bf = (const float*)d_in[6];
    const float* u  = (const float*)d_in[7];
    const int*   src = (const int*)d_in[8];
    const int*   dst = (const int*)d_in[9];
    float* out = (float*)d_out;

    const int E = in_sizes[8];
    const int N = in_sizes[0] / 256;   // h is (L=2, N, D=128)

    prep_all_kernel<<<257, 256>>>(W0, W1, Wf, b1, bf);

    cudaFuncSetAttribute(advers_mask_edge_mma,
                         cudaFuncAttributeMaxDynamicSharedMemorySize, SM_TOTAL);
    int blocks = (E + 127) / 128;
    advers_mask_edge_mma<<<blocks, 256, SM_TOTAL>>>(h, b0, u, src, dst, out, E, N);
}

// round 13
// speedup vs baseline: 2.2438x; 1.0184x over previous
#include <cuda_runtime.h>
#include <cuda_fp16.h>
#include <math.h>
#include <stdint.h>

// ---------------- device globals (allowed scratch) ----------------
__device__ float g_wv[2][128];   // wv[c] = Wf[c] @ W1
__device__ float g_cc[2];        // cc[c] = bf[c] + Wf[c] @ b1
// B images: [seg][split] = 128dp x 128k fp16, row stride 256B, 64B-window swizzle
__device__ __half g_w0img[4][2][16384];

// A-tile swizzle (128B window): off = row*256 + (kByte ^ ((row&7)<<4))
__host__ __device__ __forceinline__ uint32_t swzA(int row, int kByte) {
    return (uint32_t)row * 256u + (uint32_t)(kByte ^ ((row & 7) << 4));
}
// B-image swizzle (64B window): off = row*256 + (kByte ^ (((row>>1)&3)<<4))
__host__ __device__ __forceinline__ uint32_t swzB(int row, int kByte) {
    return (uint32_t)row * 256u + (uint32_t)(kByte ^ (((row >> 1) & 3) << 4));
}

// ---------------- PTX helpers (sm_80+, legal on plain sm_100) ----------------
__device__ __forceinline__ uint32_t smem_u32(const void* p) {
    uint32_t a;
    asm("{ .reg .u64 t; cvta.to.shared.u64 t, %1; cvt.u32.u64 %0, t; }" : "=r"(a) : "l"(p));
    return a;
}
__device__ __forceinline__ void ldsm_x4(uint32_t* d, uint32_t addr) {
    asm volatile("ldmatrix.sync.aligned.m8n8.x4.shared.b16 {%0,%1,%2,%3}, [%4];"
                 : "=r"(d[0]), "=r"(d[1]), "=r"(d[2]), "=r"(d[3]) : "r"(addr));
}
__device__ __forceinline__ void mma_fp16(float* c, const uint32_t* a, uint32_t b0, uint32_t b1) {
    asm volatile(
        "mma.sync.aligned.m16n8k16.row.col.f32.f16.f16.f32 "
        "{%0,%1,%2,%3}, {%4,%5,%6,%7}, {%8,%9}, {%0,%1,%2,%3};"
        : "+f"(c[0]), "+f"(c[1]), "+f"(c[2]), "+f"(c[3])
        : "r"(a[0]), "r"(a[1]), "r"(a[2]), "r"(a[3]), "r"(b0), "r"(b1));
}
__device__ __forceinline__ void cp_async16(uint32_t dst, const void* src) {
    asm volatile("cp.async.cg.shared.global [%0], [%1], 16;" :: "r"(dst), "l"(src));
}
__device__ __forceinline__ void cp_commit() { asm volatile("cp.async.commit_group;" ::: "memory"); }
__device__ __forceinline__ void cp_wait0()  { asm volatile("cp.async.wait_group 0;" ::: "memory"); }

// ---------------- fused prep ----------------
__global__ void prep_all_kernel(const float* __restrict__ W0,
                                const float* __restrict__ W1,
                                const float* __restrict__ Wf,
                                const float* __restrict__ b1,
                                const float* __restrict__ bf) {
    if (blockIdx.x < 256) {
        int idx = blockIdx.x * 256 + threadIdx.x;   // 65536 = 4seg*128dp*128k
        int seg = idx >> 14;
        int dp  = (idx >> 7) & 127;
        int k   = idx & 127;
        float w = W0[dp * 512 + seg * 128 + k];
        __half v0 = __float2half_rn(w);
        float r1 = w - __half2float(v0);
        __half v1 = __float2half_rn(r1);
        uint32_t o = swzB(dp, k * 2) >> 1;
        g_w0img[seg][0][o] = v0;
        g_w0img[seg][1][o] = v1;
    } else {
        int t = threadIdx.x;
        int c = t >> 7, d = t & 127;
        double s = 0.0;
        for (int j = 0; j < 128; j++)
            s += (double)Wf[c * 128 + j] * (double)W1[j * 128 + d];
        g_wv[c][d] = (float)s;
        if (t < 2) {
            double cs = 0.0;
            for (int j = 0; j < 128; j++)
                cs += (double)Wf[t * 128 + j] * (double)b1[j];
            g_cc[t] = (float)(cs + (double)bf[t]);
        }
    }
}

// ---------------- main kernel ----------------
// Block: 128 edges x 128 dp, 256 threads = 8 warps. Warp tile: 32e x 64dp.
// K loop: 16 chunks of 32k (4 segs x 4 quarters). A rebuilt per seg (full 128k);
// B double-buffered 16KB chunks via cp.async, prefetch distance 1.
// smem:
//   [0,     65536)  A: 2 splits x (128e x 128k fp16, swizzled 128B-window, stride 256B)
//   [65536, 98304)  B: 2 bufs x (2 splits x 128dp x 32k fp16, 64B rows, 64B-window swz)
//   [98304, 99840)  consts: b0[128], wv0[128], wv1[128]
//   [99840,101888)  s_red[2][128][2]
#define SM_A     0
#define SM_B     65536
#define SM_CONST 98304
#define SM_RED   99840
#define SM_TOTAL 101888

__global__ void __launch_bounds__(256, 2)
advers_mask_edge_mma(const float* __restrict__ h,
                     const float* __restrict__ b0,
                     const float* __restrict__ u,
                     const int* __restrict__ src,
                     const int* __restrict__ dst,
                     float* __restrict__ out,
                     int E, int N) {
    extern __shared__ char smem[];
    const uint32_t sbase = smem_u32(smem);
    float* sc   = (float*)(smem + SM_CONST);
    float* sred = (float*)(smem + SM_RED);

    const int tid = threadIdx.x;
    const int wid = tid >> 5;
    const int lid = tid & 31;
    const int we  = wid >> 1;     // 0..3 edge group
    const int wd  = wid & 1;      // 0..1 dp half
    const int eb  = blockIdx.x * 128;

    if (tid < 128) {
        sc[tid]       = b0[tid];
        sc[128 + tid] = g_wv[0][tid];
        sc[256 + tid] = g_wv[1][tid];
    }

    // A-build assignment: 2 threads per edge (k halves of 64)
    const int e_local = tid >> 1;
    const int khalf   = (tid & 1) * 64;
    int eg = eb + e_local;
    int ec = (eg < E) ? eg : (E - 1);
    const int se = src[ec];
    const int de = dst[ec];

    // ldmatrix per-lane addressing
    const int g = lid >> 3, r = lid & 7;
    uint32_t aRowTerm[2];
#pragma unroll
    for (int mt = 0; mt < 2; mt++)
        aRowTerm[mt] = (uint32_t)(we * 32 + mt * 16 + (g & 1) * 8 + r) * 256u;
    uint32_t bRowTerm[4];
#pragma unroll
    for (int nt2 = 0; nt2 < 4; nt2++)
        bRowTerm[nt2] = (uint32_t)(wd * 64 + nt2 * 16 + (g >> 1) * 8 + r) * 64u;  // 64B stride
    const uint32_t aKsel = (uint32_t)((g >> 1) * 16);
    const uint32_t bKsel = (uint32_t)((g & 1) * 16);
    const uint32_t rx    = (uint32_t)(r << 4);            // A: 128B-window swz
    const uint32_t rbx   = (uint32_t)(((r >> 1) & 3) << 4); // B: 64B-window swz

    float acc[2][8][4];
#pragma unroll
    for (int mt = 0; mt < 2; mt++)
#pragma unroll
        for (int nt = 0; nt < 8; nt++)
#pragma unroll
            for (int i = 0; i < 4; i++) acc[mt][nt][i] = 0.f;

    // ---- prologue: prefetch B chunk 0 into buf 0 ----
    {
        const char* bsrc = (const char*)&g_w0img[0][0][0];
        uint32_t dst0 = sbase + SM_B;
#pragma unroll
        for (int i = 0; i < 4; i++) {
            int idx = tid + i * 256;
            int s = idx >> 9, j = idx & 511, row = j >> 2, gg = j & 3;
            cp_async16(dst0 + s * 8192 + row * 64 + gg * 16,
                       bsrc + s * 32768 + row * 256 + gg * 16);
        }
        cp_commit();
    }

    for (int cg = 0; cg < 16; cg++) {
        const int buf = cg & 1;
        cp_wait0();          // my B(cg) copies arrived
        __syncthreads();     // all B(cg) visible; all warps retired MMA(cg-1)

        // prefetch B(cg+1) into freed buffer — flies during this chunk's MMA
        if (cg + 1 < 16) {
            const int seg_n = (cg + 1) >> 2, sub_n = (cg + 1) & 3;
            const char* bsrc = (const char*)&g_w0img[seg_n][0][0];
            uint32_t dst0 = sbase + SM_B + (uint32_t)(buf ^ 1) * 16384u;
#pragma unroll
            for (int i = 0; i < 4; i++) {
                int idx = tid + i * 256;
                int s = idx >> 9, j = idx & 511, row = j >> 2, gg = j & 3;
                cp_async16(dst0 + s * 8192 + row * 64 + gg * 16,
                           bsrc + s * 32768 + row * 256 + sub_n * 64 + gg * 16);
            }
            cp_commit();
        }

        // ---- rebuild A at seg starts (reads retired by the barrier above) ----
        if ((cg & 3) == 0) {
            const int seg = cg >> 2;
            const int l0 = seg >> 1, l1 = seg & 1;
            const float* hs = h + ((size_t)l0 * N + se) * 128;
            const float* hd = h + ((size_t)l1 * N + de) * 128;
#pragma unroll
            for (int q = 0; q < 8; q++) {
                const int col = khalf + q * 8;
                float4 a1 = *(const float4*)(hs + col);
                float4 a2 = *(const float4*)(hs + col + 4);
                float4 d1 = *(const float4*)(hd + col);
                float4 d2 = *(const float4*)(hd + col + 4);
                float p[8] = {a1.x * d1.x, a1.y * d1.y, a1.z * d1.z, a1.w * d1.w,
                              a2.x * d2.x, a2.y * d2.y, a2.z * d2.z, a2.w * d2.w};
                uint32_t u0[4], u1[4];
#pragma unroll
                for (int pi = 0; pi < 4; pi++) {
                    float p0 = p[2 * pi], p1 = p[2 * pi + 1];
                    __half h0a = __float2half_rn(p0);
                    __half h0b = __float2half_rn(p1);
                    float r0 = p0 - __half2float(h0a);
                    float r1f = p1 - __half2float(h0b);
                    __half h1a = __float2half_rn(r0);
                    __half h1b = __float2half_rn(r1f);
                    u0[pi] = (uint32_t)__half_as_ushort(h0a) | ((uint32_t)__half_as_ushort(h0b) << 16);
                    u1[pi] = (uint32_t)__half_as_ushort(h1a) | ((uint32_t)__half_as_ushort(h1b) << 16);
                }
                uint32_t soff = swzA(e_local, col * 2);
                *(uint4*)(smem + SM_A + soff)         = make_uint4(u0[0], u0[1], u0[2], u0[3]);
                *(uint4*)(smem + SM_A + 32768 + soff) = make_uint4(u1[0], u1[1], u1[2], u1[3]);
            }
            __syncthreads();   // A visible before MMA
        }

        // ---- MMA chunk: 2 K-steps of 16; 3 split-combos ----
        const uint32_t bbase = sbase + SM_B + (uint32_t)buf * 16384u;
#pragma unroll
        for (int kst = 0; kst < 2; kst++) {
            const uint32_t akb = (uint32_t)((cg & 3) * 64 + kst * 32 + aKsel) ^ rx;
            const uint32_t bkb = (uint32_t)(kst * 32 + bKsel) ^ rbx;

            uint32_t afr[2][2][4];
#pragma unroll
            for (int s = 0; s < 2; s++)
#pragma unroll
                for (int mt = 0; mt < 2; mt++)
                    ldsm_x4(afr[s][mt], sbase + SM_A + s * 32768 + aRowTerm[mt] + akb);

#pragma unroll
            for (int nt2 = 0; nt2 < 4; nt2++) {
                uint32_t bf0[4], bf1[4];
                ldsm_x4(bf0, bbase + bRowTerm[nt2] + bkb);          // split 0
                ldsm_x4(bf1, bbase + 8192 + bRowTerm[nt2] + bkb);   // split 1
#pragma unroll
                for (int mt = 0; mt < 2; mt++) {
                    float* c0 = acc[mt][nt2 * 2 + 0];
                    float* c1 = acc[mt][nt2 * 2 + 1];
                    mma_fp16(c0, afr[0][mt], bf0[0], bf0[1]);   // a0*b0
                    mma_fp16(c1, afr[0][mt], bf0[2], bf0[3]);
                    mma_fp16(c0, afr[0][mt], bf1[0], bf1[1]);   // a0*b1
                    mma_fp16(c1, afr[0][mt], bf1[2], bf1[3]);
                    mma_fp16(c0, afr[1][mt], bf0[0], bf0[1]);   // a1*b0
                    mma_fp16(c1, afr[1][mt], bf0[2], bf0[3]);
                }
            }
        }
    }
    __syncthreads();   // final chunk reads retired (next phase reuses smem regions only via sred)

    // ---- epilogue: relu + dual dot from C fragments ----
    const int tig = lid & 3;
#pragma unroll
    for (int mt = 0; mt < 2; mt++) {
#pragma unroll
        for (int hr = 0; hr < 2; hr++) {
            float s0 = 0.f, s1 = 0.f;
#pragma unroll
            for (int nt = 0; nt < 8; nt++) {
                int dp0 = wd * 64 + (nt >> 1) * 16 + (nt & 1) * 8 + tig * 2;
                float x0 = fmaxf(acc[mt][nt][hr * 2 + 0] + sc[dp0], 0.f);
                float x1 = fmaxf(acc[mt][nt][hr * 2 + 1] + sc[dp0 + 1], 0.f);
                s0 = fmaf(x0, sc[128 + dp0], fmaf(x1, sc[128 + dp0 + 1], s0));
                s1 = fmaf(x0, sc[256 + dp0], fmaf(x1, sc[256 + dp0 + 1], s1));
            }
            s0 += __shfl_xor_sync(0xffffffffu, s0, 1);
            s0 += __shfl_xor_sync(0xffffffffu, s0, 2);
            s1 += __shfl_xor_sync(0xffffffffu, s1, 1);
            s1 += __shfl_xor_sync(0xffffffffu, s1, 2);
            if (tig == 0) {
                int e_row = we * 32 + mt * 16 + hr * 8 + (lid >> 2);
                sred[(wd * 128 + e_row) * 2 + 0] = s0;
                sred[(wd * 128 + e_row) * 2 + 1] = s1;
            }
        }
    }
    __syncthreads();

    if (tid < 128) {
        int e = eb + tid;
        if (e < E) {
            float s0 = sred[tid * 2 + 0] + sred[(128 + tid) * 2 + 0];
            float s1 = sred[tid * 2 + 1] + sred[(128 + tid) * 2 + 1];
            float u0 = u[2 * e], u1 = u[2 * e + 1];
            float gg0 = -logf(-logf(u0 + 1e-10f) + 1e-10f);
            float gg1 = -logf(-logf(u1 + 1e-10f) + 1e-10f);
            float v0 = s0 + g_cc[0] + gg0;
            float v1 = s1 + g_cc[1] + gg1;
            bool one = (v1 > v0);   // argmax ties -> class 0
            out[2 * e]     = one ? 0.f : 1.f;
            out[2 * e + 1] = one ? 1.f : 0.f;
        }
    }
}

extern "C" void kernel_launch(void* const* d_in, const int* in_sizes, int n_in,
                              void* d_out, int out_size) {
    const float* h  = (const float*)d_in[0];
    const float* W0 = (const float*)d_in[1];
    const float* b0 = (const float*)d_in[2];
    const float* W1 = (const float*)d_in[3];
    const float* b1 = (const float*)d_in[4];
    const float* Wf = (const float*)d_in[5];
    const float* bf = (const float*)d_in[6];
    const float* u  = (const float*)d_in[7];
    const int*   src = (const int*)d_in[8];
    const int*   dst = (const int*)d_in[9];
    float* out = (float*)d_out;

    const int E = in_sizes[8];
    const int N = in_sizes[0] / 256;   // h is (L=2, N, D=128)

    prep_all_kernel<<<257, 256>>>(W0, W1, Wf, b1, bf);

    cudaFuncSetAttribute(advers_mask_edge_mma,
                         cudaFuncAttributeMaxDynamicSharedMemorySize, SM_TOTAL);
    int blocks = (E + 127) / 128;
    advers_mask_edge_mma<<<blocks, 256, SM_TOTAL>>>(h, b0, u, src, dst, out, E, N);
}

// round 14
// speedup vs baseline: 4.4174x; 1.9687x over previous
#include <cuda_runtime.h>
#include <cuda_fp16.h>
#include <math.h>
#include <stdint.h>

// ---------------- device globals (allowed scratch) ----------------
__device__ float g_wv[2][128];   // wv[c] = Wf[c] @ W1
__device__ float g_cc[2];        // cc[c] = bf[c] + Wf[c] @ b1
// B images: [seg][split] = 128dp x 128k fp16, row stride 256B, 64B-window swizzle
__device__ __half g_w0img[4][2][16384];

// A-tile swizzle (128B window): off = row*256 + (kByte ^ ((row&7)<<4))
__host__ __device__ __forceinline__ uint32_t swzA(int row, int kByte) {
    return (uint32_t)row * 256u + (uint32_t)(kByte ^ ((row & 7) << 4));
}
// B-image swizzle (64B window): off = row*256 + (kByte ^ (((row>>1)&3)<<4))
__host__ __device__ __forceinline__ uint32_t swzB(int row, int kByte) {
    return (uint32_t)row * 256u + (uint32_t)(kByte ^ (((row >> 1) & 3) << 4));
}

// ---------------- PTX helpers (sm_80+, legal on plain sm_100) ----------------
__device__ __forceinline__ uint32_t smem_u32(const void* p) {
    uint32_t a;
    asm("{ .reg .u64 t; cvta.to.shared.u64 t, %1; cvt.u32.u64 %0, t; }" : "=r"(a) : "l"(p));
    return a;
}
__device__ __forceinline__ void ldsm_x4(uint32_t* d, uint32_t addr) {
    asm volatile("ldmatrix.sync.aligned.m8n8.x4.shared.b16 {%0,%1,%2,%3}, [%4];"
                 : "=r"(d[0]), "=r"(d[1]), "=r"(d[2]), "=r"(d[3]) : "r"(addr));
}
__device__ __forceinline__ void mma_fp16(float* c, const uint32_t* a, uint32_t b0, uint32_t b1) {
    asm volatile(
        "mma.sync.aligned.m16n8k16.row.col.f32.f16.f16.f32 "
        "{%0,%1,%2,%3}, {%4,%5,%6,%7}, {%8,%9}, {%0,%1,%2,%3};"
        : "+f"(c[0]), "+f"(c[1]), "+f"(c[2]), "+f"(c[3])
        : "r"(a[0]), "r"(a[1]), "r"(a[2]), "r"(a[3]), "r"(b0), "r"(b1));
}
__device__ __forceinline__ void cp_async16(uint32_t dst, const void* src) {
    asm volatile("cp.async.cg.shared.global [%0], [%1], 16;" :: "r"(dst), "l"(src));
}
__device__ __forceinline__ void cp_commit() { asm volatile("cp.async.commit_group;" ::: "memory"); }
__device__ __forceinline__ void cp_wait0()  { asm volatile("cp.async.wait_group 0;" ::: "memory"); }

// ---------------- fused prep ----------------
__global__ void prep_all_kernel(const float* __restrict__ W0,
                                const float* __restrict__ W1,
                                const float* __restrict__ Wf,
                                const float* __restrict__ b1,
                                const float* __restrict__ bf) {
    if (blockIdx.x < 256) {
        int idx = blockIdx.x * 256 + threadIdx.x;   // 65536 = 4seg*128dp*128k
        int seg = idx >> 14;
        int dp  = (idx >> 7) & 127;
        int k   = idx & 127;
        float w = W0[dp * 512 + seg * 128 + k];
        __half v0 = __float2half_rn(w);
        float r1 = w - __half2float(v0);
        __half v1 = __float2half_rn(r1);
        uint32_t o = swzB(dp, k * 2) >> 1;
        g_w0img[seg][0][o] = v0;
        g_w0img[seg][1][o] = v1;
    } else {
        int t = threadIdx.x;
        int c = t >> 7, d = t & 127;
        double s = 0.0;
        for (int j = 0; j < 128; j++)
            s += (double)Wf[c * 128 + j] * (double)W1[j * 128 + d];
        g_wv[c][d] = (float)s;
        if (t < 2) {
            double cs = 0.0;
            for (int j = 0; j < 128; j++)
                cs += (double)Wf[t * 128 + j] * (double)b1[j];
            g_cc[t] = (float)(cs + (double)bf[t]);
        }
    }
}

// ---------------- main kernel ----------------
// Block: 128 edges x 128 dp, 256 threads = 8 warps. Warp tile: 32e x 64dp.
// K loop: 16 chunks of 32k (4 segs x 4 quarters). A rebuilt per seg (full 128k)
// with WARP-COOPERATIVE COALESCED row gathers (1 warp loads one 512B h row).
// B double-buffered 16KB chunks via cp.async, prefetch distance 1.
// smem:
//   [0,     65536)  A: 2 splits x (128e x 128k fp16, 128B-window swz, stride 256B)
//   [65536, 98304)  B: 2 bufs x (2 splits x 128dp x 32k fp16, 64B rows, 64B-window swz)
//   [98304, 99840)  consts: b0[128], wv0[128], wv1[128]
//   [99840,101888)  s_red[2][128][2]
#define SM_A     0
#define SM_B     65536
#define SM_CONST 98304
#define SM_RED   99840
#define SM_TOTAL 101888

__global__ void __launch_bounds__(256, 2)
advers_mask_edge_mma(const float* __restrict__ h,
                     const float* __restrict__ b0,
                     const float* __restrict__ u,
                     const int* __restrict__ src,
                     const int* __restrict__ dst,
                     float* __restrict__ out,
                     int E, int N) {
    extern __shared__ char smem[];
    const uint32_t sbase = smem_u32(smem);
    float* sc   = (float*)(smem + SM_CONST);
    float* sred = (float*)(smem + SM_RED);

    const int tid = threadIdx.x;
    const int wid = tid >> 5;
    const int lid = tid & 31;
    const int we  = wid >> 1;     // 0..3 edge group
    const int wd  = wid & 1;      // 0..1 dp half
    const int eb  = blockIdx.x * 128;

    if (tid < 128) {
        sc[tid]       = b0[tid];
        sc[128 + tid] = g_wv[0][tid];
        sc[256 + tid] = g_wv[1][tid];
    }

    // ---- pre-gather edge indices: warp owns 16 edges; lanes 0-15 hold src,
    //      lanes 16-31 hold dst (broadcast later via shfl) ----
    int myidx;
    {
        int e = eb + wid * 16 + (lid & 15);
        if (e >= E) e = E - 1;
        myidx = (lid < 16) ? src[e] : dst[e];
    }

    // ldmatrix per-lane addressing (fragment mapping unchanged from R11/R12)
    const int g = lid >> 3, r = lid & 7;
    uint32_t aRowTerm[2];
#pragma unroll
    for (int mt = 0; mt < 2; mt++)
        aRowTerm[mt] = (uint32_t)(we * 32 + mt * 16 + (g & 1) * 8 + r) * 256u;
    uint32_t bRowTerm[4];
#pragma unroll
    for (int nt2 = 0; nt2 < 4; nt2++)
        bRowTerm[nt2] = (uint32_t)(wd * 64 + nt2 * 16 + (g >> 1) * 8 + r) * 64u;  // 64B stride
    const uint32_t aKsel = (uint32_t)((g >> 1) * 16);
    const uint32_t bKsel = (uint32_t)((g & 1) * 16);
    const uint32_t rx    = (uint32_t)(r << 4);              // A: 128B-window swz
    const uint32_t rbx   = (uint32_t)(((r >> 1) & 3) << 4); // B: 64B-window swz

    float acc[2][8][4];
#pragma unroll
    for (int mt = 0; mt < 2; mt++)
#pragma unroll
        for (int nt = 0; nt < 8; nt++)
#pragma unroll
            for (int i = 0; i < 4; i++) acc[mt][nt][i] = 0.f;

    // ---- prologue: prefetch B chunk 0 into buf 0 ----
    {
        const char* bsrc = (const char*)&g_w0img[0][0][0];
        uint32_t dst0 = sbase + SM_B;
#pragma unroll
        for (int i = 0; i < 4; i++) {
            int idx = tid + i * 256;
            int s = idx >> 9, j = idx & 511, row = j >> 2, gg = j & 3;
            cp_async16(dst0 + s * 8192 + row * 64 + gg * 16,
                       bsrc + s * 32768 + row * 256 + gg * 16);
        }
        cp_commit();
    }

    for (int cg = 0; cg < 16; cg++) {
        const int buf = cg & 1;
        cp_wait0();          // B(cg) copies arrived
        __syncthreads();     // all B(cg) visible; all warps retired MMA(cg-1)

        // prefetch B(cg+1) into freed buffer — flies during this chunk's MMA
        if (cg + 1 < 16) {
            const int seg_n = (cg + 1) >> 2, sub_n = (cg + 1) & 3;
            const char* bsrc = (const char*)&g_w0img[seg_n][0][0];
            uint32_t dst0 = sbase + SM_B + (uint32_t)(buf ^ 1) * 16384u;
#pragma unroll
            for (int i = 0; i < 4; i++) {
                int idx = tid + i * 256;
                int s = idx >> 9, j = idx & 511, row = j >> 2, gg = j & 3;
                cp_async16(dst0 + s * 8192 + row * 64 + gg * 16,
                           bsrc + s * 32768 + row * 256 + sub_n * 64 + gg * 16);
            }
            cp_commit();
        }

        // ---- rebuild A at seg starts: warp-cooperative coalesced gathers ----
        if ((cg & 3) == 0) {
            const int seg = cg >> 2;
            const int l0 = seg >> 1, l1 = seg & 1;
            const float* hsB = h + (size_t)l0 * N * 128;
            const float* hdB = h + (size_t)l1 * N * 128;
            const int e_base = wid * 16;

#pragma unroll
            for (int g4 = 0; g4 < 4; g4++) {
                // stage 4 edges: 8 coalesced row loads in flight
                float4 sv[4], dv[4];
#pragma unroll
                for (int j = 0; j < 4; j++) {
                    int ee = g4 * 4 + j;
                    int se = __shfl_sync(0xffffffffu, myidx, ee);
                    int de = __shfl_sync(0xffffffffu, myidx, 16 + ee);
                    sv[j] = *(const float4*)(hsB + (size_t)se * 128 + lid * 4);
                    dv[j] = *(const float4*)(hdB + (size_t)de * 128 + lid * 4);
                }
#pragma unroll
                for (int j = 0; j < 4; j++) {
                    int row = e_base + g4 * 4 + j;
                    float p0 = sv[j].x * dv[j].x;
                    float p1 = sv[j].y * dv[j].y;
                    float p2 = sv[j].z * dv[j].z;
                    float p3 = sv[j].w * dv[j].w;
                    __half a0 = __float2half_rn(p0), a1h = __float2half_rn(p1);
                    __half a2 = __float2half_rn(p2), a3 = __float2half_rn(p3);
                    float q0 = p0 - __half2float(a0), q1 = p1 - __half2float(a1h);
                    float q2 = p2 - __half2float(a2), q3 = p3 - __half2float(a3);
                    uint32_t u0a = (uint32_t)__half_as_ushort(a0) |
                                   ((uint32_t)__half_as_ushort(a1h) << 16);
                    uint32_t u0b = (uint32_t)__half_as_ushort(a2) |
                                   ((uint32_t)__half_as_ushort(a3) << 16);
                    __half b0h = __float2half_rn(q0), b1h = __float2half_rn(q1);
                    __half b2h = __float2half_rn(q2), b3h = __float2half_rn(q3);
                    uint32_t u1a = (uint32_t)__half_as_ushort(b0h) |
                                   ((uint32_t)__half_as_ushort(b1h) << 16);
                    uint32_t u1b = (uint32_t)__half_as_ushort(b2h) |
                                   ((uint32_t)__half_as_ushort(b3h) << 16);
                    uint32_t soff = swzA(row, lid * 8);   // lane covers fp16 cols 4l..4l+3
                    *(uint2*)(smem + SM_A + soff)         = make_uint2(u0a, u0b);
                    *(uint2*)(smem + SM_A + 32768 + soff) = make_uint2(u1a, u1b);
                }
            }
            __syncthreads();   // A visible before MMA
        }

        // ---- MMA chunk: 2 K-steps of 16; 3 split-combos (a0b0, a0b1, a1b0) ----
        const uint32_t bbase = sbase + SM_B + (uint32_t)buf * 16384u;
#pragma unroll
        for (int kst = 0; kst < 2; kst++) {
            const uint32_t akb = (uint32_t)((cg & 3) * 64 + kst * 32 + aKsel) ^ rx;
            const uint32_t bkb = (uint32_t)(kst * 32 + bKsel) ^ rbx;

            uint32_t afr[2][2][4];
#pragma unroll
            for (int s = 0; s < 2; s++)
#pragma unroll
                for (int mt = 0; mt < 2; mt++)
                    ldsm_x4(afr[s][mt], sbase + SM_A + s * 32768 + aRowTerm[mt] + akb);

#pragma unroll
            for (int nt2 = 0; nt2 < 4; nt2++) {
                uint32_t bf0[4], bf1[4];
                ldsm_x4(bf0, bbase + bRowTerm[nt2] + bkb);          // split 0
                ldsm_x4(bf1, bbase + 8192 + bRowTerm[nt2] + bkb);   // split 1
#pragma unroll
                for (int mt = 0; mt < 2; mt++) {
                    float* c0 = acc[mt][nt2 * 2 + 0];
                    float* c1 = acc[mt][nt2 * 2 + 1];
                    mma_fp16(c0, afr[0][mt], bf0[0], bf0[1]);   // a0*b0
                    mma_fp16(c1, afr[0][mt], bf0[2], bf0[3]);
                    mma_fp16(c0, afr[0][mt], bf1[0], bf1[1]);   // a0*b1
                    mma_fp16(c1, afr[0][mt], bf1[2], bf1[3]);
                    mma_fp16(c0, afr[1][mt], bf0[0], bf0[1]);   // a1*b0
                    mma_fp16(c1, afr[1][mt], bf0[2], bf0[3]);
                }
            }
        }
    }
    __syncthreads();

    // ---- epilogue: relu + dual dot from C fragments ----
    const int tig = lid & 3;
#pragma unroll
    for (int mt = 0; mt < 2; mt++) {
#pragma unroll
        for (int hr = 0; hr < 2; hr++) {
            float s0 = 0.f, s1 = 0.f;
#pragma unroll
            for (int nt = 0; nt < 8; nt++) {
                int dp0 = wd * 64 + (nt >> 1) * 16 + (nt & 1) * 8 + tig * 2;
                float x0 = fmaxf(acc[mt][nt][hr * 2 + 0] + sc[dp0], 0.f);
                float x1 = fmaxf(acc[mt][nt][hr * 2 + 1] + sc[dp0 + 1], 0.f);
                s0 = fmaf(x0, sc[128 + dp0], fmaf(x1, sc[128 + dp0 + 1], s0));
                s1 = fmaf(x0, sc[256 + dp0], fmaf(x1, sc[256 + dp0 + 1], s1));
            }
            s0 += __shfl_xor_sync(0xffffffffu, s0, 1);
            s0 += __shfl_xor_sync(0xffffffffu, s0, 2);
            s1 += __shfl_xor_sync(0xffffffffu, s1, 1);
            s1 += __shfl_xor_sync(0xffffffffu, s1, 2);
            if (tig == 0) {
                int e_row = we * 32 + mt * 16 + hr * 8 + (lid >> 2);
                sred[(wd * 128 + e_row) * 2 + 0] = s0;
                sred[(wd * 128 + e_row) * 2 + 1] = s1;
            }
        }
    }
    __syncthreads();

    if (tid < 128) {
        int e = eb + tid;
        if (e < E) {
            float s0 = sred[tid * 2 + 0] + sred[(128 + tid) * 2 + 0];
            float s1 = sred[tid * 2 + 1] + sred[(128 + tid) * 2 + 1];
            float u0 = u[2 * e], u1 = u[2 * e + 1];
            float gg0 = -logf(-logf(u0 + 1e-10f) + 1e-10f);
            float gg1 = -logf(-logf(u1 + 1e-10f) + 1e-10f);
            float v0 = s0 + g_cc[0] + gg0;
            float v1 = s1 + g_cc[1] + gg1;
            bool one = (v1 > v0);   // argmax ties -> class 0
            out[2 * e]     = one ? 0.f : 1.f;
            out[2 * e + 1] = one ? 1.f : 0.f;
        }
    }
}

extern "C" void kernel_launch(void* const* d_in, const int* in_sizes, int n_in,
                              void* d_out, int out_size) {
    const float* h  = (const float*)d_in[0];
    const float* W0 = (const float*)d_in[1];
    const float* b0 = (const float*)d_in[2];
    const float* W1 = (const float*)d_in[3];
    const float* b1 = (const float*)d_in[4];
    const float* Wf = (const float*)d_in[5];
    const float* bf = (const float*)d_in[6];
    const float* u  = (const float*)d_in[7];
    const int*   src = (const int*)d_in[8];
    const int*   dst = (const int*)d_in[9];
    float* out = (float*)d_out;

    const int E = in_sizes[8];
    const int N = in_sizes[0] / 256;   // h is (L=2, N, D=128)

    prep_all_kernel<<<257, 256>>>(W0, W1, Wf, b1, bf);

    cudaFuncSetAttribute(advers_mask_edge_mma,
                         cudaFuncAttributeMaxDynamicSharedMemorySize, SM_TOTAL);
    int blocks = (E + 127) / 128;
    advers_mask_edge_mma<<<blocks, 256, SM_TOTAL>>>(h, b0, u, src, dst, out, E, N);
}